// round 2
// baseline (speedup 1.0000x reference)
#include <cuda_runtime.h>
#include <cfloat>

#define BB 8
#define NN 2048
#define KNBR 32
#define NPTS (BB*NN)

// ---------------- scratch (static device globals; no runtime alloc) ----------
__device__ float g_d2[(size_t)NPTS * NN];    // 134MB pairwise distances (reused per stage)
__device__ float g_sq[NPTS];
__device__ int   g_idx[NPTS * KNBR];
__device__ float g_x1[NPTS * 64];
__device__ float g_x2[NPTS * 128];
__device__ float g_xc[NPTS * 192];
__device__ float g_qp[(size_t)NPTS * 1024];  // [q | p] per point, max 2*512
__device__ float g_wc[192 * 1024];           // combined weights [Wb | Wa-Wb]

// ---------------- squared norms ----------------------------------------------
__global__ void sq_kernel(const float* __restrict__ X, float* __restrict__ sq, int C) {
    int i = blockIdx.x * blockDim.x + threadIdx.x;
    if (i < NPTS) {
        const float* r = X + (size_t)i * C;
        float s = 0.f;
        for (int c = 0; c < C; c++) s += r[c] * r[c];
        sq[i] = s;
    }
}

// ---------------- pairwise d2: 128x128 tile, 8x8/thread -----------------------
// grid (N/128, N/128, B), 256 threads
__global__ void __launch_bounds__(256, 2)
d2_kernel(const float* __restrict__ X, const float* __restrict__ sq,
          float* __restrict__ d2, int C) {
    __shared__ __align__(16) float As[16][132];
    __shared__ __align__(16) float Bs[16][132];
    int b = blockIdx.z;
    int row0 = blockIdx.y * 128, col0 = blockIdx.x * 128;
    const float* Xb = X + (size_t)b * NN * C;
    int tid = threadIdx.x;
    int ty = tid >> 4, tx = tid & 15;
    float acc[8][8];
#pragma unroll
    for (int i = 0; i < 8; i++)
#pragma unroll
        for (int j = 0; j < 8; j++) acc[i][j] = 0.f;

    int kk = tid & 15, i0 = tid >> 4;

    for (int k0 = 0; k0 < C; k0 += 16) {
        int k = k0 + kk;
        bool kin = (k < C);
#pragma unroll
        for (int u = 0; u < 8; u++) {
            int i = i0 + (u << 4);
            As[kk][i] = kin ? Xb[(size_t)(row0 + i) * C + k] : 0.f;
            Bs[kk][i] = kin ? Xb[(size_t)(col0 + i) * C + k] : 0.f;
        }
        __syncthreads();
#pragma unroll
        for (int t = 0; t < 16; t++) {
            float a[8], bv[8];
            *(float4*)&a[0]  = *(const float4*)&As[t][ty << 2];
            *(float4*)&a[4]  = *(const float4*)&As[t][64 + (ty << 2)];
            *(float4*)&bv[0] = *(const float4*)&Bs[t][tx << 2];
            *(float4*)&bv[4] = *(const float4*)&Bs[t][64 + (tx << 2)];
#pragma unroll
            for (int i = 0; i < 8; i++)
#pragma unroll
                for (int j = 0; j < 8; j++) acc[i][j] += a[i] * bv[j];
        }
        __syncthreads();
    }
#pragma unroll
    for (int i = 0; i < 8; i++) {
        int r = row0 + ((i < 4) ? ((ty << 2) + i) : (64 + (ty << 2) + i - 4));
        float sqr = sq[b * NN + r];
        float* outrow = d2 + ((size_t)b * NN + r) * NN;
#pragma unroll
        for (int j = 0; j < 8; j++) {
            int c = col0 + ((j < 4) ? ((tx << 2) + j) : (64 + (tx << 2) + j - 4));
            float v = sqr + sq[b * NN + c] - 2.f * acc[i][j];
            if (r == c) v = FLT_MAX;
            outrow[c] = v;
        }
    }
}

// ---------------- top-K selection (barrier-free per-warp select + rank merge) --
// one block (8 warps) per query row. Phase 1: each warp extracts its sorted
// top-32 of its 256 elements using only warp shuffles (register-resident).
// Phase 2: all 256 threads compute the global rank of their candidate via
// binary search in the 7 other sorted lists; rank<32 writes output.
__global__ void knn_kernel(const float* __restrict__ d2, int* __restrict__ idxout) {
    __shared__ float lv[8][32];
    __shared__ int   li[8][32];
    int p = blockIdx.x;
    const float* row = d2 + (size_t)p * NN;
    int w = threadIdx.x >> 5, lane = threadIdx.x & 31;
    int base = w << 8;  // w*256

    float v[8];
#pragma unroll
    for (int u = 0; u < 8; u++) v[u] = row[base + (u << 5) + lane];

    float bv = v[0]; int bu = 0;
#pragma unroll
    for (int u = 1; u < 8; u++) if (v[u] < bv) { bv = v[u]; bu = u; }
    int bi = base + (bu << 5) + lane;

    for (int s = 0; s < KNBR; s++) {
        float rv = bv; int ri = bi;
#pragma unroll
        for (int off = 16; off; off >>= 1) {
            float ov = __shfl_xor_sync(0xffffffffu, rv, off);
            int   oi = __shfl_xor_sync(0xffffffffu, ri, off);
            if (ov < rv || (ov == rv && oi < ri)) { rv = ov; ri = oi; }
        }
        if (lane == (ri & 31)) {
            int uu = (ri - base) >> 5;
#pragma unroll
            for (int u = 0; u < 8; u++) if (u == uu) v[u] = FLT_MAX;
            bv = v[0]; bu = 0;
#pragma unroll
            for (int u = 1; u < 8; u++) if (v[u] < bv) { bv = v[u]; bu = u; }
            bi = base + (bu << 5) + lane;
        }
        if (lane == 0) { lv[w][s] = rv; li[w][s] = ri; }
    }
    __syncthreads();

    // phase 2: rank-based merge across the 8 sorted lists
    float mv = lv[w][lane];
    int   mi = li[w][lane];
    int rank = lane;  // position in own (sorted, strictly ordered) list
#pragma unroll
    for (int o = 0; o < 8; o++) {
        if (o == w) continue;
        int cnt = 0;
#pragma unroll
        for (int step = 32; step; step >>= 1) {
            int t = cnt + step;
            if (t <= 32) {
                float ov = lv[o][t - 1]; int oi = li[o][t - 1];
                if (ov < mv || (ov == mv && oi < mi)) cnt = t;
            }
        }
        rank += cnt;
    }
    if (rank < KNBR) idxout[p * KNBR + rank] = mi;
}

// ---------------- combined weight prep: wc = [Wb | Wa - Wb] -------------------
__global__ void prepw_kernel(const float* __restrict__ W, float* __restrict__ wc,
                             int C, int Cout) {
    int i = blockIdx.x * blockDim.x + threadIdx.x;
    if (i < C * Cout) {
        int c = i / Cout, d = i % Cout;
        float wa = W[c * Cout + d];
        float wb = W[(C + c) * Cout + d];
        wc[c * (2 * Cout) + d] = wb;
        wc[c * (2 * Cout) + Cout + d] = wa - wb;
    }
}

// ---------------- generic GEMM: C[M,N] = A[M,K] @ B[K,N] ----------------------
// grid (N/128, M/128), 256 threads, 128x128 tile, 8x8 per thread
__global__ void __launch_bounds__(256, 2)
gemm_kernel(const float* __restrict__ A, const float* __restrict__ Bm,
            float* __restrict__ Cm, int Kd, int Nd) {
    __shared__ __align__(16) float As[16][132];
    __shared__ __align__(16) float Bs[16][132];
    int row0 = blockIdx.y * 128, col0 = blockIdx.x * 128;
    int tid = threadIdx.x;
    int ty = tid >> 4, tx = tid & 15;
    float acc[8][8];
#pragma unroll
    for (int i = 0; i < 8; i++)
#pragma unroll
        for (int j = 0; j < 8; j++) acc[i][j] = 0.f;

    int kk = tid & 15, i0 = tid >> 4;      // A-load mapping
    int j0 = tid & 127, kb = tid >> 7;     // B-load mapping

    for (int k0 = 0; k0 < Kd; k0 += 16) {
        int k = k0 + kk;
        bool kin = (k < Kd);
#pragma unroll
        for (int u = 0; u < 8; u++) {
            int i = i0 + (u << 4);
            As[kk][i] = kin ? A[(size_t)(row0 + i) * Kd + k] : 0.f;
        }
#pragma unroll
        for (int u = 0; u < 8; u++) {
            int kr = kb + (u << 1);
            int kg = k0 + kr;
            Bs[kr][j0] = (kg < Kd) ? Bm[(size_t)kg * Nd + col0 + j0] : 0.f;
        }
        __syncthreads();
#pragma unroll
        for (int t = 0; t < 16; t++) {
            float a[8], bv[8];
            *(float4*)&a[0]  = *(const float4*)&As[t][ty << 2];
            *(float4*)&a[4]  = *(const float4*)&As[t][64 + (ty << 2)];
            *(float4*)&bv[0] = *(const float4*)&Bs[t][tx << 2];
            *(float4*)&bv[4] = *(const float4*)&Bs[t][64 + (tx << 2)];
#pragma unroll
            for (int i = 0; i < 8; i++)
#pragma unroll
                for (int j = 0; j < 8; j++) acc[i][j] += a[i] * bv[j];
        }
        __syncthreads();
    }
#pragma unroll
    for (int i = 0; i < 8; i++) {
        int r = row0 + ((i < 4) ? ((ty << 2) + i) : (64 + (ty << 2) + i - 4));
        float4 v0 = make_float4(acc[i][0], acc[i][1], acc[i][2], acc[i][3]);
        float4 v1 = make_float4(acc[i][4], acc[i][5], acc[i][6], acc[i][7]);
        *(float4*)&Cm[(size_t)r * Nd + col0 + (tx << 2)]      = v0;
        *(float4*)&Cm[(size_t)r * Nd + col0 + 64 + (tx << 2)] = v1;
    }
}

// ---------------- gather-max + bias + activation ------------------------------
__global__ void gather_kernel(const float* __restrict__ qp, const int* __restrict__ idx,
                              const float* __restrict__ bias, float* __restrict__ out,
                              int Cout, int relu) {
    __shared__ int nbr[KNBR];
    int p = blockIdx.x;
    int b = p / NN;
    if (threadIdx.x < KNBR) nbr[threadIdx.x] = idx[p * KNBR + threadIdx.x];
    __syncthreads();
    int ld = 2 * Cout;
    size_t baserow = (size_t)b * NN;
    for (int d = threadIdx.x; d < Cout; d += blockDim.x) {
        float m = -FLT_MAX;
#pragma unroll 4
        for (int j = 0; j < KNBR; j++) {
            m = fmaxf(m, qp[(baserow + nbr[j]) * ld + d]);
        }
        float v = qp[(size_t)p * ld + Cout + d] + bias[d] + m;
        if (relu) v = fmaxf(v, 0.f);
        out[(size_t)p * Cout + d] = v;
    }
}

// ---------------- concat x1 | x2 ----------------------------------------------
__global__ void concat_kernel(const float* __restrict__ x1, const float* __restrict__ x2,
                              float* __restrict__ xc) {
    int i = blockIdx.x * blockDim.x + threadIdx.x;
    if (i < NPTS * 192) {
        int p = i / 192, c = i % 192;
        xc[i] = (c < 64) ? x1[p * 64 + c] : x2[p * 128 + (c - 64)];
    }
}

// ---------------- launch ------------------------------------------------------
extern "C" void kernel_launch(void* const* d_in, const int* in_sizes, int n_in,
                              void* d_out, int out_size) {
    const float* x  = (const float*)d_in[0];
    const float* W1 = (const float*)d_in[1];
    const float* b1 = (const float*)d_in[2];
    const float* W2 = (const float*)d_in[3];
    const float* b2 = (const float*)d_in[4];
    const float* W3 = (const float*)d_in[5];
    const float* b3 = (const float*)d_in[6];
    float* out = (float*)d_out;

    float *d2, *sqp, *x1, *x2, *xc, *qp, *wc;
    int* idxp;
    cudaGetSymbolAddress((void**)&d2,   g_d2);
    cudaGetSymbolAddress((void**)&sqp,  g_sq);
    cudaGetSymbolAddress((void**)&idxp, g_idx);
    cudaGetSymbolAddress((void**)&x1,   g_x1);
    cudaGetSymbolAddress((void**)&x2,   g_x2);
    cudaGetSymbolAddress((void**)&xc,   g_xc);
    cudaGetSymbolAddress((void**)&qp,   g_qp);
    cudaGetSymbolAddress((void**)&wc,   g_wc);

    dim3 d2grid(NN / 128, NN / 128, BB);

    // ---- stage 1: C=3 -> 64   (knn placed 4th so ncu -s 5 -c 1 lands on it)
    sq_kernel<<<(NPTS + 255) / 256, 256>>>(x, sqp, 3);
    d2_kernel<<<d2grid, 256>>>(x, sqp, d2, 3);
    prepw_kernel<<<(3 * 64 + 255) / 256, 256>>>(W1, wc, 3, 64);
    knn_kernel<<<NPTS, 256>>>(d2, idxp);
    gemm_kernel<<<dim3(128 / 128, NPTS / 128), 256>>>(x, wc, qp, 3, 128);
    gather_kernel<<<NPTS, 64>>>(qp, idxp, b1, x1, 64, 1);

    // ---- stage 2: C=64 -> 128
    sq_kernel<<<(NPTS + 255) / 256, 256>>>(x1, sqp, 64);
    d2_kernel<<<d2grid, 256>>>(x1, sqp, d2, 64);
    prepw_kernel<<<(64 * 128 + 255) / 256, 256>>>(W2, wc, 64, 128);
    knn_kernel<<<NPTS, 256>>>(d2, idxp);
    gemm_kernel<<<dim3(256 / 128, NPTS / 128), 256>>>(x1, wc, qp, 64, 256);
    gather_kernel<<<NPTS, 128>>>(qp, idxp, b2, x2, 128, 1);

    // ---- stage 3: knn on x2 (C=128), conv on concat(x1,x2) (C=192) -> 512
    sq_kernel<<<(NPTS + 255) / 256, 256>>>(x2, sqp, 128);
    d2_kernel<<<d2grid, 256>>>(x2, sqp, d2, 128);
    prepw_kernel<<<(192 * 512 + 255) / 256, 256>>>(W3, wc, 192, 512);
    knn_kernel<<<NPTS, 256>>>(d2, idxp);
    concat_kernel<<<(NPTS * 192 + 255) / 256, 256>>>(x1, x2, xc);
    gemm_kernel<<<dim3(1024 / 128, NPTS / 128), 256>>>(xc, wc, qp, 192, 1024);
    gather_kernel<<<NPTS, 256>>>(qp, idxp, b3, out, 512, 0);
}

// round 3
// speedup vs baseline: 2.1032x; 2.1032x over previous
#include <cuda_runtime.h>
#include <cfloat>

#define BB 8
#define NN 2048
#define KNBR 32
#define NPTS (BB*NN)

// ---------------- scratch (static device globals; no runtime alloc) ----------
__device__ float g_d2[(size_t)NPTS * NN];    // 134MB pairwise distances (reused per stage)
__device__ float g_sq[NPTS];
__device__ int   g_idx[NPTS * KNBR];
__device__ float g_x1[NPTS * 64];
__device__ float g_x2[NPTS * 128];
__device__ float g_xc[NPTS * 192];
__device__ float g_qp[(size_t)NPTS * 1024];  // [q | p] per point, max 2*512
__device__ float g_wc[192 * 1024];           // combined weights [Wb | Wa-Wb]

// ---------------- squared norms ----------------------------------------------
__global__ void sq_kernel(const float* __restrict__ X, float* __restrict__ sq, int C) {
    int i = blockIdx.x * blockDim.x + threadIdx.x;
    if (i < NPTS) {
        const float* r = X + (size_t)i * C;
        float s = 0.f;
        for (int c = 0; c < C; c++) s += r[c] * r[c];
        sq[i] = s;
    }
}

// ---------------- pairwise d2: 128x128 tile, 8x8/thread -----------------------
__global__ void __launch_bounds__(256, 2)
d2_kernel(const float* __restrict__ X, const float* __restrict__ sq,
          float* __restrict__ d2, int C) {
    __shared__ __align__(16) float As[16][132];
    __shared__ __align__(16) float Bs[16][132];
    int b = blockIdx.z;
    int row0 = blockIdx.y * 128, col0 = blockIdx.x * 128;
    const float* Xb = X + (size_t)b * NN * C;
    int tid = threadIdx.x;
    int ty = tid >> 4, tx = tid & 15;
    float acc[8][8];
#pragma unroll
    for (int i = 0; i < 8; i++)
#pragma unroll
        for (int j = 0; j < 8; j++) acc[i][j] = 0.f;

    int kk = tid & 15, i0 = tid >> 4;

    for (int k0 = 0; k0 < C; k0 += 16) {
        int k = k0 + kk;
        bool kin = (k < C);
#pragma unroll
        for (int u = 0; u < 8; u++) {
            int i = i0 + (u << 4);
            As[kk][i] = kin ? Xb[(size_t)(row0 + i) * C + k] : 0.f;
            Bs[kk][i] = kin ? Xb[(size_t)(col0 + i) * C + k] : 0.f;
        }
        __syncthreads();
#pragma unroll
        for (int t = 0; t < 16; t++) {
            float a[8], bv[8];
            *(float4*)&a[0]  = *(const float4*)&As[t][ty << 2];
            *(float4*)&a[4]  = *(const float4*)&As[t][64 + (ty << 2)];
            *(float4*)&bv[0] = *(const float4*)&Bs[t][tx << 2];
            *(float4*)&bv[4] = *(const float4*)&Bs[t][64 + (tx << 2)];
#pragma unroll
            for (int i = 0; i < 8; i++)
#pragma unroll
                for (int j = 0; j < 8; j++) acc[i][j] += a[i] * bv[j];
        }
        __syncthreads();
    }
#pragma unroll
    for (int i = 0; i < 8; i++) {
        int r = row0 + ((i < 4) ? ((ty << 2) + i) : (64 + (ty << 2) + i - 4));
        float sqr = sq[b * NN + r];
        float* outrow = d2 + ((size_t)b * NN + r) * NN;
#pragma unroll
        for (int j = 0; j < 8; j++) {
            int c = col0 + ((j < 4) ? ((tx << 2) + j) : (64 + (tx << 2) + j - 4));
            float v = sqr + sq[b * NN + c] - 2.f * acc[i][j];
            if (r == c) v = FLT_MAX;
            outrow[c] = v;
        }
    }
}

// ---------------- top-K via 3-pass radix select --------------------------------
// One 256-thread block per row. Keys = monotone uint mapping of float d2.
// Pass bits: 11 / 11 / 10  -> exact value T of the 32nd-smallest key.
// Emit all keys < T (order irrelevant: consumer takes max over the set),
// then fill remaining slots with lowest-index keys == T (matches stable top_k).
__global__ void __launch_bounds__(256)
knn_kernel(const float* __restrict__ d2, int* __restrict__ idxout) {
    __shared__ unsigned keys[NN];      // 8KB
    __shared__ int hist[2048];         // 8KB (reused as tie-index buffer at the end)
    __shared__ int wsum[8], wsumex[8];
    __shared__ int ctrlB, ctrlBelow;
    __shared__ int cnt, eqcnt;

    int p = blockIdx.x;
    int t = threadIdx.x, lane = t & 31, wid = t >> 5;

    // load row, map to order-preserving unsigned keys
    const float4* row4 = (const float4*)(d2 + (size_t)p * NN);
#pragma unroll
    for (int u = 0; u < 2; u++) {
        int i4 = t + (u << 8);
        float4 f = row4[i4];
        unsigned b;
        b = __float_as_uint(f.x); keys[i4 * 4 + 0] = (b & 0x80000000u) ? ~b : (b | 0x80000000u);
        b = __float_as_uint(f.y); keys[i4 * 4 + 1] = (b & 0x80000000u) ? ~b : (b | 0x80000000u);
        b = __float_as_uint(f.z); keys[i4 * 4 + 2] = (b & 0x80000000u) ? ~b : (b | 0x80000000u);
        b = __float_as_uint(f.w); keys[i4 * 4 + 3] = (b & 0x80000000u) ? ~b : (b | 0x80000000u);
    }
    __syncthreads();

    unsigned pval = 0, pmask = 0;
    int base = 0;
#pragma unroll
    for (int pass = 0; pass < 3; pass++) {
        const int shift = (pass == 0) ? 21 : (pass == 1) ? 10 : 0;
        const int nbins = (pass == 2) ? 1024 : 2048;
        for (int i = t; i < nbins; i += 256) hist[i] = 0;
        __syncthreads();
#pragma unroll
        for (int u = 0; u < 8; u++) {
            unsigned k = keys[t + (u << 8)];
            if ((k & pmask) == pval) atomicAdd(&hist[(k >> shift) & (nbins - 1)], 1);
        }
        __syncthreads();
        const int seg = nbins >> 8;
        const int b0 = t * seg;
        int s = 0;
        for (int j = 0; j < seg; j++) s += hist[b0 + j];
        int incl = s;
#pragma unroll
        for (int off = 1; off < 32; off <<= 1) {
            int n = __shfl_up_sync(0xffffffffu, incl, off);
            if (lane >= off) incl += n;
        }
        if (lane == 31) wsum[wid] = incl;
        __syncthreads();
        if (t == 0) {
            int run = 0;
            for (int w = 0; w < 8; w++) { wsumex[w] = run; run += wsum[w]; }
        }
        __syncthreads();
        int excl = wsumex[wid] + incl - s;
        int need = KNBR - base;
        if (excl < need && need <= excl + s) {   // exactly one thread matches
            int run = excl;
            for (int j = 0; j < seg; j++) {
                int c = hist[b0 + j];
                if (run + c >= need) { ctrlB = b0 + j; ctrlBelow = run; break; }
                run += c;
            }
        }
        __syncthreads();
        base += ctrlBelow;
        pval |= ((unsigned)ctrlB) << shift;
        pmask |= ((unsigned)(nbins - 1)) << shift;
        __syncthreads();   // hist & ctrl are rewritten next pass
    }

    const unsigned T = pval;               // value of the 32nd-smallest key
    if (t == 0) { cnt = 0; eqcnt = 0; }
    __syncthreads();
#pragma unroll
    for (int u = 0; u < 8; u++) {
        int i = t + (u << 8);
        unsigned k = keys[i];
        if (k < T) {
            int pos = atomicAdd(&cnt, 1);
            idxout[p * KNBR + pos] = i;
        } else if (k == T) {
            int e = atomicAdd(&eqcnt, 1);
            hist[e] = i;                    // hist reused; eqcnt <= 2048 always
        }
    }
    __syncthreads();
    int c = cnt, E = eqcnt, tn = KNBR - c;  // tn >= 1 by construction
    if (E == tn) {
        for (int j = t; j < E; j += 256) idxout[p * KNBR + c + j] = hist[j];
    } else {
        // take the tn lowest indices among the E ties
        for (int j = t; j < E; j += 256) {
            int mi = hist[j], r = 0;
            for (int q = 0; q < E; q++) r += (hist[q] < mi);
            if (r < tn) idxout[p * KNBR + c + r] = mi;
        }
    }
}

// ---------------- combined weight prep: wc = [Wb | Wa - Wb] -------------------
__global__ void prepw_kernel(const float* __restrict__ W, float* __restrict__ wc,
                             int C, int Cout) {
    int i = blockIdx.x * blockDim.x + threadIdx.x;
    if (i < C * Cout) {
        int c = i / Cout, d = i % Cout;
        float wa = W[c * Cout + d];
        float wb = W[(C + c) * Cout + d];
        wc[c * (2 * Cout) + d] = wb;
        wc[c * (2 * Cout) + Cout + d] = wa - wb;
    }
}

// ---------------- generic GEMM: C[M,N] = A[M,K] @ B[K,N] ----------------------
__global__ void __launch_bounds__(256, 2)
gemm_kernel(const float* __restrict__ A, const float* __restrict__ Bm,
            float* __restrict__ Cm, int Kd, int Nd) {
    __shared__ __align__(16) float As[16][132];
    __shared__ __align__(16) float Bs[16][132];
    int row0 = blockIdx.y * 128, col0 = blockIdx.x * 128;
    int tid = threadIdx.x;
    int ty = tid >> 4, tx = tid & 15;
    float acc[8][8];
#pragma unroll
    for (int i = 0; i < 8; i++)
#pragma unroll
        for (int j = 0; j < 8; j++) acc[i][j] = 0.f;

    int kk = tid & 15, i0 = tid >> 4;
    int j0 = tid & 127, kb = tid >> 7;

    for (int k0 = 0; k0 < Kd; k0 += 16) {
        int k = k0 + kk;
        bool kin = (k < Kd);
#pragma unroll
        for (int u = 0; u < 8; u++) {
            int i = i0 + (u << 4);
            As[kk][i] = kin ? A[(size_t)(row0 + i) * Kd + k] : 0.f;
        }
#pragma unroll
        for (int u = 0; u < 8; u++) {
            int kr = kb + (u << 1);
            int kg = k0 + kr;
            Bs[kr][j0] = (kg < Kd) ? Bm[(size_t)kg * Nd + col0 + j0] : 0.f;
        }
        __syncthreads();
#pragma unroll
        for (int t = 0; t < 16; t++) {
            float a[8], bv[8];
            *(float4*)&a[0]  = *(const float4*)&As[t][ty << 2];
            *(float4*)&a[4]  = *(const float4*)&As[t][64 + (ty << 2)];
            *(float4*)&bv[0] = *(const float4*)&Bs[t][tx << 2];
            *(float4*)&bv[4] = *(const float4*)&Bs[t][64 + (tx << 2)];
#pragma unroll
            for (int i = 0; i < 8; i++)
#pragma unroll
                for (int j = 0; j < 8; j++) acc[i][j] += a[i] * bv[j];
        }
        __syncthreads();
    }
#pragma unroll
    for (int i = 0; i < 8; i++) {
        int r = row0 + ((i < 4) ? ((ty << 2) + i) : (64 + (ty << 2) + i - 4));
        float4 v0 = make_float4(acc[i][0], acc[i][1], acc[i][2], acc[i][3]);
        float4 v1 = make_float4(acc[i][4], acc[i][5], acc[i][6], acc[i][7]);
        *(float4*)&Cm[(size_t)r * Nd + col0 + (tx << 2)]      = v0;
        *(float4*)&Cm[(size_t)r * Nd + col0 + 64 + (tx << 2)] = v1;
    }
}

// ---------------- gather-max + bias + activation ------------------------------
__global__ void gather_kernel(const float* __restrict__ qp, const int* __restrict__ idx,
                              const float* __restrict__ bias, float* __restrict__ out,
                              int Cout, int relu) {
    __shared__ int nbr[KNBR];
    int p = blockIdx.x;
    int b = p / NN;
    if (threadIdx.x < KNBR) nbr[threadIdx.x] = idx[p * KNBR + threadIdx.x];
    __syncthreads();
    int ld = 2 * Cout;
    size_t baserow = (size_t)b * NN;
    for (int d = threadIdx.x; d < Cout; d += blockDim.x) {
        float m = -FLT_MAX;
#pragma unroll 4
        for (int j = 0; j < KNBR; j++) {
            m = fmaxf(m, qp[(baserow + nbr[j]) * ld + d]);
        }
        float v = qp[(size_t)p * ld + Cout + d] + bias[d] + m;
        if (relu) v = fmaxf(v, 0.f);
        out[(size_t)p * Cout + d] = v;
    }
}

// ---------------- concat x1 | x2 ----------------------------------------------
__global__ void concat_kernel(const float* __restrict__ x1, const float* __restrict__ x2,
                              float* __restrict__ xc) {
    int i = blockIdx.x * blockDim.x + threadIdx.x;
    if (i < NPTS * 192) {
        int p = i / 192, c = i % 192;
        xc[i] = (c < 64) ? x1[p * 64 + c] : x2[p * 128 + (c - 64)];
    }
}

// ---------------- launch ------------------------------------------------------
extern "C" void kernel_launch(void* const* d_in, const int* in_sizes, int n_in,
                              void* d_out, int out_size) {
    const float* x  = (const float*)d_in[0];
    const float* W1 = (const float*)d_in[1];
    const float* b1 = (const float*)d_in[2];
    const float* W2 = (const float*)d_in[3];
    const float* b2 = (const float*)d_in[4];
    const float* W3 = (const float*)d_in[5];
    const float* b3 = (const float*)d_in[6];
    float* out = (float*)d_out;

    float *d2, *sqp, *x1, *x2, *xc, *qp, *wc;
    int* idxp;
    cudaGetSymbolAddress((void**)&d2,   g_d2);
    cudaGetSymbolAddress((void**)&sqp,  g_sq);
    cudaGetSymbolAddress((void**)&idxp, g_idx);
    cudaGetSymbolAddress((void**)&x1,   g_x1);
    cudaGetSymbolAddress((void**)&x2,   g_x2);
    cudaGetSymbolAddress((void**)&xc,   g_xc);
    cudaGetSymbolAddress((void**)&qp,   g_qp);
    cudaGetSymbolAddress((void**)&wc,   g_wc);

    dim3 d2grid(NN / 128, NN / 128, BB);

    // ---- stage 1: C=3 -> 64
    sq_kernel<<<(NPTS + 255) / 256, 256>>>(x, sqp, 3);
    d2_kernel<<<d2grid, 256>>>(x, sqp, d2, 3);
    prepw_kernel<<<(3 * 64 + 255) / 256, 256>>>(W1, wc, 3, 64);
    knn_kernel<<<NPTS, 256>>>(d2, idxp);
    gemm_kernel<<<dim3(128 / 128, NPTS / 128), 256>>>(x, wc, qp, 3, 128);
    gather_kernel<<<NPTS, 64>>>(qp, idxp, b1, x1, 64, 1);

    // ---- stage 2: C=64 -> 128
    sq_kernel<<<(NPTS + 255) / 256, 256>>>(x1, sqp, 64);
    d2_kernel<<<d2grid, 256>>>(x1, sqp, d2, 64);
    prepw_kernel<<<(64 * 128 + 255) / 256, 256>>>(W2, wc, 64, 128);
    knn_kernel<<<NPTS, 256>>>(d2, idxp);
    gemm_kernel<<<dim3(256 / 128, NPTS / 128), 256>>>(x1, wc, qp, 64, 256);
    gather_kernel<<<NPTS, 128>>>(qp, idxp, b2, x2, 128, 1);

    // ---- stage 3: knn on x2 (C=128), conv on concat(x1,x2) (C=192) -> 512
    sq_kernel<<<(NPTS + 255) / 256, 256>>>(x2, sqp, 128);
    d2_kernel<<<d2grid, 256>>>(x2, sqp, d2, 128);
    prepw_kernel<<<(192 * 512 + 255) / 256, 256>>>(W3, wc, 192, 512);
    knn_kernel<<<NPTS, 256>>>(d2, idxp);
    concat_kernel<<<(NPTS * 192 + 255) / 256, 256>>>(x1, x2, xc);
    gemm_kernel<<<dim3(1024 / 128, NPTS / 128), 256>>>(xc, wc, qp, 192, 1024);
    gather_kernel<<<NPTS, 256>>>(qp, idxp, b3, out, 512, 0);
}

// round 4
// speedup vs baseline: 2.6335x; 1.2522x over previous
#include <cuda_runtime.h>
#include <cfloat>

#define BB 8
#define NN 2048
#define KNBR 32
#define NPTS (BB*NN)
#define NBLK (NN/128)          // 16 tiles per dim
#define NPAIR (NBLK*(NBLK+1)/2) // 136 upper-tri block pairs

// ---------------- scratch (static device globals; no runtime alloc) ----------
__device__ float g_d2[(size_t)NPTS * NN];    // 134MB pairwise distances (reused per stage)
__device__ float g_sq[NPTS];
__device__ int   g_idx[NPTS * KNBR];
__device__ float g_x1[NPTS * 64];
__device__ float g_x2[NPTS * 128];
__device__ float g_xc[NPTS * 192];
__device__ float g_qp[(size_t)NPTS * 1024];  // [q | p] per point, max 2*512
__device__ float g_wc[192 * 1024];           // combined weights [Wb | Wa-Wb]

// ---------------- squared norms ----------------------------------------------
__global__ void sq_kernel(const float* __restrict__ X, float* __restrict__ sq, int C) {
    int i = blockIdx.x * blockDim.x + threadIdx.x;
    if (i < NPTS) {
        const float* r = X + (size_t)i * C;
        float s = 0.f;
        for (int c = 0; c < C; c++) s += r[c] * r[c];
        sq[i] = s;
    }
}

// ---------------- pairwise d2, symmetric: upper-tri blocks only ---------------
// grid (NPAIR, B), 256 threads, 128x128 tile, 8x8/thread.
// Off-diagonal tiles are written twice (direct + transposed from registers).
__global__ void __launch_bounds__(256, 2)
d2sym_kernel(const float* __restrict__ X, const float* __restrict__ sq,
             float* __restrict__ d2, int C) {
    __shared__ __align__(16) float As[16][132];
    __shared__ __align__(16) float Bs[16][132];
    int b = blockIdx.y;
    // decode upper-tri pair index -> (bi, bj), bi <= bj
    int rem = blockIdx.x, bi = 0;
    while (rem >= NBLK - bi) { rem -= NBLK - bi; bi++; }
    int bj = bi + rem;
    int row0 = bi * 128, col0 = bj * 128;

    const float* Xb = X + (size_t)b * NN * C;
    int tid = threadIdx.x;
    int ty = tid >> 4, tx = tid & 15;
    float acc[8][8];
#pragma unroll
    for (int i = 0; i < 8; i++)
#pragma unroll
        for (int j = 0; j < 8; j++) acc[i][j] = 0.f;

    int kk = tid & 15, i0 = tid >> 4;

    for (int k0 = 0; k0 < C; k0 += 16) {
        int k = k0 + kk;
        bool kin = (k < C);
#pragma unroll
        for (int u = 0; u < 8; u++) {
            int i = i0 + (u << 4);
            As[kk][i] = kin ? Xb[(size_t)(row0 + i) * C + k] : 0.f;
            Bs[kk][i] = kin ? Xb[(size_t)(col0 + i) * C + k] : 0.f;
        }
        __syncthreads();
#pragma unroll
        for (int t = 0; t < 16; t++) {
            float a[8], bv[8];
            *(float4*)&a[0]  = *(const float4*)&As[t][ty << 2];
            *(float4*)&a[4]  = *(const float4*)&As[t][64 + (ty << 2)];
            *(float4*)&bv[0] = *(const float4*)&Bs[t][tx << 2];
            *(float4*)&bv[4] = *(const float4*)&Bs[t][64 + (tx << 2)];
#pragma unroll
            for (int i = 0; i < 8; i++)
#pragma unroll
                for (int j = 0; j < 8; j++) acc[i][j] += a[i] * bv[j];
        }
        __syncthreads();
    }

    // transform acc -> final d2 values in registers
#pragma unroll
    for (int i = 0; i < 8; i++) {
        int r = row0 + ((i < 4) ? ((ty << 2) + i) : (64 + (ty << 2) + i - 4));
        float sqr = sq[b * NN + r];
#pragma unroll
        for (int j = 0; j < 8; j++) {
            int c = col0 + ((j < 4) ? ((tx << 2) + j) : (64 + (tx << 2) + j - 4));
            float v = sqr + sq[b * NN + c] - 2.f * acc[i][j];
            if (r == c) v = FLT_MAX;      // only possible when bi == bj
            acc[i][j] = v;
        }
    }

    float* d2b = d2 + (size_t)b * NN * NN;
    // direct write (coalesced float4)
#pragma unroll
    for (int i = 0; i < 8; i++) {
        int r = row0 + ((i < 4) ? ((ty << 2) + i) : (64 + (ty << 2) + i - 4));
        float4 v0 = make_float4(acc[i][0], acc[i][1], acc[i][2], acc[i][3]);
        float4 v1 = make_float4(acc[i][4], acc[i][5], acc[i][6], acc[i][7]);
        *(float4*)&d2b[(size_t)r * NN + col0 + (tx << 2)]      = v0;
        *(float4*)&d2b[(size_t)r * NN + col0 + 64 + (tx << 2)] = v1;
    }
    // mirrored write for off-diagonal tiles (float4 along r; full 32B sectors)
    if (bi != bj) {
#pragma unroll
        for (int j = 0; j < 8; j++) {
            int c = col0 + ((j < 4) ? ((tx << 2) + j) : (64 + (tx << 2) + j - 4));
            float4 lo = make_float4(acc[0][j], acc[1][j], acc[2][j], acc[3][j]);
            float4 hi = make_float4(acc[4][j], acc[5][j], acc[6][j], acc[7][j]);
            *(float4*)&d2b[(size_t)c * NN + row0 + (ty << 2)]      = lo;
            *(float4*)&d2b[(size_t)c * NN + row0 + 64 + (ty << 2)] = hi;
        }
    }
}

// ---------------- top-K via 3-pass radix select (register-resident keys) ------
// One 256-thread block per row; 8 keys/thread in registers, smem = histogram only.
__global__ void __launch_bounds__(256)
knn_kernel(const float* __restrict__ d2, int* __restrict__ idxout) {
    __shared__ int hist[2048];         // 8KB (reused as tie-index buffer at the end)
    __shared__ int wsum[8], wsumex[8];
    __shared__ int ctrlB, ctrlBelow;
    __shared__ int cnt, eqcnt;

    int p = blockIdx.x;
    int t = threadIdx.x, lane = t & 31, wid = t >> 5;

    // load 8 elements per thread -> order-preserving unsigned keys in registers
    // element index of key[e]: 4*t + ((e>>2)<<10) + (e&3)
    const float4* row4 = (const float4*)(d2 + (size_t)p * NN);
    unsigned key[8];
#pragma unroll
    for (int u = 0; u < 2; u++) {
        float4 f = row4[t + (u << 8)];
        unsigned bx;
        bx = __float_as_uint(f.x); key[u * 4 + 0] = (bx & 0x80000000u) ? ~bx : (bx | 0x80000000u);
        bx = __float_as_uint(f.y); key[u * 4 + 1] = (bx & 0x80000000u) ? ~bx : (bx | 0x80000000u);
        bx = __float_as_uint(f.z); key[u * 4 + 2] = (bx & 0x80000000u) ? ~bx : (bx | 0x80000000u);
        bx = __float_as_uint(f.w); key[u * 4 + 3] = (bx & 0x80000000u) ? ~bx : (bx | 0x80000000u);
    }

    unsigned pval = 0, pmask = 0;
    int base = 0;
#pragma unroll
    for (int pass = 0; pass < 3; pass++) {
        const int shift = (pass == 0) ? 21 : (pass == 1) ? 10 : 0;
        const int nbins = (pass == 2) ? 1024 : 2048;
        for (int i = t; i < nbins; i += 256) hist[i] = 0;
        __syncthreads();
#pragma unroll
        for (int e = 0; e < 8; e++) {
            unsigned k = key[e];
            if ((k & pmask) == pval) atomicAdd(&hist[(k >> shift) & (nbins - 1)], 1);
        }
        __syncthreads();
        const int seg = nbins >> 8;
        const int b0 = t * seg;
        int s = 0;
        for (int j = 0; j < seg; j++) s += hist[b0 + j];
        int incl = s;
#pragma unroll
        for (int off = 1; off < 32; off <<= 1) {
            int n = __shfl_up_sync(0xffffffffu, incl, off);
            if (lane >= off) incl += n;
        }
        if (lane == 31) wsum[wid] = incl;
        __syncthreads();
        if (t == 0) {
            int run = 0;
            for (int w = 0; w < 8; w++) { wsumex[w] = run; run += wsum[w]; }
        }
        __syncthreads();
        int excl = wsumex[wid] + incl - s;
        int need = KNBR - base;
        if (excl < need && need <= excl + s) {   // exactly one thread matches
            int run = excl;
            for (int j = 0; j < seg; j++) {
                int c = hist[b0 + j];
                if (run + c >= need) { ctrlB = b0 + j; ctrlBelow = run; break; }
                run += c;
            }
        }
        __syncthreads();
        base += ctrlBelow;
        pval |= ((unsigned)ctrlB) << shift;
        pmask |= ((unsigned)(nbins - 1)) << shift;
        __syncthreads();   // hist & ctrl are rewritten next pass
    }

    const unsigned T = pval;               // value of the 32nd-smallest key
    if (t == 0) { cnt = 0; eqcnt = 0; }
    __syncthreads();
#pragma unroll
    for (int e = 0; e < 8; e++) {
        unsigned k = key[e];
        int i = (t << 2) + ((e >> 2) << 10) + (e & 3);
        if (k < T) {
            int pos = atomicAdd(&cnt, 1);
            idxout[p * KNBR + pos] = i;
        } else if (k == T) {
            int q = atomicAdd(&eqcnt, 1);
            hist[q] = i;                    // hist reused; eqcnt <= 2048 always
        }
    }
    __syncthreads();
    int c = cnt, E = eqcnt, tn = KNBR - c;  // tn >= 1 by construction
    if (E == tn) {
        for (int j = t; j < E; j += 256) idxout[p * KNBR + c + j] = hist[j];
    } else {
        // take the tn lowest indices among the E ties
        for (int j = t; j < E; j += 256) {
            int mi = hist[j], r = 0;
            for (int q = 0; q < E; q++) r += (hist[q] < mi);
            if (r < tn) idxout[p * KNBR + c + r] = mi;
        }
    }
}

// ---------------- combined weight prep: wc = [Wb | Wa - Wb] -------------------
__global__ void prepw_kernel(const float* __restrict__ W, float* __restrict__ wc,
                             int C, int Cout) {
    int i = blockIdx.x * blockDim.x + threadIdx.x;
    if (i < C * Cout) {
        int c = i / Cout, d = i % Cout;
        float wa = W[c * Cout + d];
        float wb = W[(C + c) * Cout + d];
        wc[c * (2 * Cout) + d] = wb;
        wc[c * (2 * Cout) + Cout + d] = wa - wb;
    }
}

// ---------------- generic GEMM: C[M,N] = A[M,K] @ B[K,N] ----------------------
__global__ void __launch_bounds__(256, 2)
gemm_kernel(const float* __restrict__ A, const float* __restrict__ Bm,
            float* __restrict__ Cm, int Kd, int Nd) {
    __shared__ __align__(16) float As[16][132];
    __shared__ __align__(16) float Bs[16][132];
    int row0 = blockIdx.y * 128, col0 = blockIdx.x * 128;
    int tid = threadIdx.x;
    int ty = tid >> 4, tx = tid & 15;
    float acc[8][8];
#pragma unroll
    for (int i = 0; i < 8; i++)
#pragma unroll
        for (int j = 0; j < 8; j++) acc[i][j] = 0.f;

    int kk = tid & 15, i0 = tid >> 4;
    int j0 = tid & 127, kb = tid >> 7;

    for (int k0 = 0; k0 < Kd; k0 += 16) {
        int k = k0 + kk;
        bool kin = (k < Kd);
#pragma unroll
        for (int u = 0; u < 8; u++) {
            int i = i0 + (u << 4);
            As[kk][i] = kin ? A[(size_t)(row0 + i) * Kd + k] : 0.f;
        }
#pragma unroll
        for (int u = 0; u < 8; u++) {
            int kr = kb + (u << 1);
            int kg = k0 + kr;
            Bs[kr][j0] = (kg < Kd) ? Bm[(size_t)kg * Nd + col0 + j0] : 0.f;
        }
        __syncthreads();
#pragma unroll
        for (int t = 0; t < 16; t++) {
            float a[8], bv[8];
            *(float4*)&a[0]  = *(const float4*)&As[t][ty << 2];
            *(float4*)&a[4]  = *(const float4*)&As[t][64 + (ty << 2)];
            *(float4*)&bv[0] = *(const float4*)&Bs[t][tx << 2];
            *(float4*)&bv[4] = *(const float4*)&Bs[t][64 + (tx << 2)];
#pragma unroll
            for (int i = 0; i < 8; i++)
#pragma unroll
                for (int j = 0; j < 8; j++) acc[i][j] += a[i] * bv[j];
        }
        __syncthreads();
    }
#pragma unroll
    for (int i = 0; i < 8; i++) {
        int r = row0 + ((i < 4) ? ((ty << 2) + i) : (64 + (ty << 2) + i - 4));
        float4 v0 = make_float4(acc[i][0], acc[i][1], acc[i][2], acc[i][3]);
        float4 v1 = make_float4(acc[i][4], acc[i][5], acc[i][6], acc[i][7]);
        *(float4*)&Cm[(size_t)r * Nd + col0 + (tx << 2)]      = v0;
        *(float4*)&Cm[(size_t)r * Nd + col0 + 64 + (tx << 2)] = v1;
    }
}

// ---------------- gather-max + bias + activation ------------------------------
__global__ void gather_kernel(const float* __restrict__ qp, const int* __restrict__ idx,
                              const float* __restrict__ bias, float* __restrict__ out,
                              int Cout, int relu) {
    __shared__ int nbr[KNBR];
    int p = blockIdx.x;
    int b = p / NN;
    if (threadIdx.x < KNBR) nbr[threadIdx.x] = idx[p * KNBR + threadIdx.x];
    __syncthreads();
    int ld = 2 * Cout;
    size_t baserow = (size_t)b * NN;
    for (int d = threadIdx.x; d < Cout; d += blockDim.x) {
        float m = -FLT_MAX;
#pragma unroll 4
        for (int j = 0; j < KNBR; j++) {
            m = fmaxf(m, qp[(baserow + nbr[j]) * ld + d]);
        }
        float v = qp[(size_t)p * ld + Cout + d] + bias[d] + m;
        if (relu) v = fmaxf(v, 0.f);
        out[(size_t)p * Cout + d] = v;
    }
}

// ---------------- concat x1 | x2 ----------------------------------------------
__global__ void concat_kernel(const float* __restrict__ x1, const float* __restrict__ x2,
                              float* __restrict__ xc) {
    int i = blockIdx.x * blockDim.x + threadIdx.x;
    if (i < NPTS * 192) {
        int p = i / 192, c = i % 192;
        xc[i] = (c < 64) ? x1[p * 64 + c] : x2[p * 128 + (c - 64)];
    }
}

// ---------------- launch ------------------------------------------------------
extern "C" void kernel_launch(void* const* d_in, const int* in_sizes, int n_in,
                              void* d_out, int out_size) {
    const float* x  = (const float*)d_in[0];
    const float* W1 = (const float*)d_in[1];
    const float* b1 = (const float*)d_in[2];
    const float* W2 = (const float*)d_in[3];
    const float* b2 = (const float*)d_in[4];
    const float* W3 = (const float*)d_in[5];
    const float* b3 = (const float*)d_in[6];
    float* out = (float*)d_out;

    float *d2, *sqp, *x1, *x2, *xc, *qp, *wc;
    int* idxp;
    cudaGetSymbolAddress((void**)&d2,   g_d2);
    cudaGetSymbolAddress((void**)&sqp,  g_sq);
    cudaGetSymbolAddress((void**)&idxp, g_idx);
    cudaGetSymbolAddress((void**)&x1,   g_x1);
    cudaGetSymbolAddress((void**)&x2,   g_x2);
    cudaGetSymbolAddress((void**)&xc,   g_xc);
    cudaGetSymbolAddress((void**)&qp,   g_qp);
    cudaGetSymbolAddress((void**)&wc,   g_wc);

    dim3 symgrid(NPAIR, BB);

    // ---- stage 1: C=3 -> 64  (d2sym placed 4th so ncu lands on it)
    sq_kernel<<<(NPTS + 255) / 256, 256>>>(x, sqp, 3);
    prepw_kernel<<<(3 * 64 + 255) / 256, 256>>>(W1, wc, 3, 64);
    gemm_kernel<<<dim3(128 / 128, NPTS / 128), 256>>>(x, wc, qp, 3, 128);
    d2sym_kernel<<<symgrid, 256>>>(x, sqp, d2, 3);
    knn_kernel<<<NPTS, 256>>>(d2, idxp);
    gather_kernel<<<NPTS, 64>>>(qp, idxp, b1, x1, 64, 1);

    // ---- stage 2: C=64 -> 128
    sq_kernel<<<(NPTS + 255) / 256, 256>>>(x1, sqp, 64);
    prepw_kernel<<<(64 * 128 + 255) / 256, 256>>>(W2, wc, 64, 128);
    gemm_kernel<<<dim3(256 / 128, NPTS / 128), 256>>>(x1, wc, qp, 64, 256);
    d2sym_kernel<<<symgrid, 256>>>(x1, sqp, d2, 64);
    knn_kernel<<<NPTS, 256>>>(d2, idxp);
    gather_kernel<<<NPTS, 128>>>(qp, idxp, b2, x2, 128, 1);

    // ---- stage 3: knn on x2 (C=128), conv on concat(x1,x2) (C=192) -> 512
    sq_kernel<<<(NPTS + 255) / 256, 256>>>(x2, sqp, 128);
    d2sym_kernel<<<symgrid, 256>>>(x2, sqp, d2, 128);
    knn_kernel<<<NPTS, 256>>>(d2, idxp);
    concat_kernel<<<(NPTS * 192 + 255) / 256, 256>>>(x1, x2, xc);
    prepw_kernel<<<(192 * 512 + 255) / 256, 256>>>(W3, wc, 192, 512);
    gemm_kernel<<<dim3(1024 / 128, NPTS / 128), 256>>>(xc, wc, qp, 192, 1024);
    gather_kernel<<<NPTS, 256>>>(qp, idxp, b3, out, 512, 0);
}

// round 5
// speedup vs baseline: 3.0547x; 1.1600x over previous
#include <cuda_runtime.h>
#include <cfloat>

#define BB 8
#define NN 2048
#define KNBR 32
#define NPTS (BB*NN)
#define NBLK (NN/128)           // 16 tiles per dim
#define NPAIR (NBLK*(NBLK+1)/2) // 136 upper-tri block pairs

typedef unsigned long long u64;

__device__ __forceinline__ u64 pack2(float lo, float hi) {
    u64 r;
    asm("mov.b64 %0, {%1, %2};" : "=l"(r) : "f"(lo), "f"(hi));
    return r;
}
__device__ __forceinline__ float2 unpack2(u64 v) {
    float2 f;
    asm("mov.b64 {%0, %1}, %2;" : "=f"(f.x), "=f"(f.y) : "l"(v));
    return f;
}
__device__ __forceinline__ void fma2(u64& d, u64 a, u64 b) {
    asm("fma.rn.f32x2 %0, %1, %2, %0;" : "+l"(d) : "l"(a), "l"(b));
}

// ---------------- scratch (static device globals; no runtime alloc) ----------
__device__ float g_d2[(size_t)NPTS * NN];    // 134MB pairwise distances (reused per stage)
__device__ float g_sq[NPTS];
__device__ int   g_idx[NPTS * KNBR];
__device__ float g_x1[NPTS * 64];
__device__ float g_x2[NPTS * 128];
__device__ float g_xc[NPTS * 192];
__device__ float g_qp[(size_t)NPTS * 1024];  // [q | p] per point, max 2*512
__device__ float g_wc[192 * 1024];           // combined weights [Wb | Wa-Wb]

// ---------------- squared norms ----------------------------------------------
__global__ void sq_kernel(const float* __restrict__ X, float* __restrict__ sq, int C) {
    int i = blockIdx.x * blockDim.x + threadIdx.x;
    if (i < NPTS) {
        const float* r = X + (size_t)i * C;
        float s = 0.f;
        for (int c = 0; c < C; c++) s += r[c] * r[c];
        sq[i] = s;
    }
}

// ---------------- pairwise d2, symmetric, FFMA2 inner loop --------------------
__global__ void __launch_bounds__(256, 2)
d2sym_kernel(const float* __restrict__ X, const float* __restrict__ sq,
             float* __restrict__ d2, int C) {
    __shared__ __align__(16) float As[16][132];
    __shared__ __align__(16) float Bs[16][132];
    int b = blockIdx.y;
    int rem = blockIdx.x, bi = 0;
    while (rem >= NBLK - bi) { rem -= NBLK - bi; bi++; }
    int bj = bi + rem;
    int row0 = bi * 128, col0 = bj * 128;

    const float* Xb = X + (size_t)b * NN * C;
    int tid = threadIdx.x;
    int ty = tid >> 4, tx = tid & 15;
    u64 acc2[8][4];
#pragma unroll
    for (int i = 0; i < 8; i++)
#pragma unroll
        for (int j = 0; j < 4; j++) acc2[i][j] = 0ull;

    int kk = tid & 15, i0 = tid >> 4;

    for (int k0 = 0; k0 < C; k0 += 16) {
        int k = k0 + kk;
        bool kin = (k < C);
#pragma unroll
        for (int u = 0; u < 8; u++) {
            int i = i0 + (u << 4);
            As[kk][i] = kin ? Xb[(size_t)(row0 + i) * C + k] : 0.f;
            Bs[kk][i] = kin ? Xb[(size_t)(col0 + i) * C + k] : 0.f;
        }
        __syncthreads();
#pragma unroll
        for (int t = 0; t < 16; t++) {
            float a[8], bv[8];
            *(float4*)&a[0]  = *(const float4*)&As[t][ty << 2];
            *(float4*)&a[4]  = *(const float4*)&As[t][64 + (ty << 2)];
            *(float4*)&bv[0] = *(const float4*)&Bs[t][tx << 2];
            *(float4*)&bv[4] = *(const float4*)&Bs[t][64 + (tx << 2)];
            u64 b2[4];
#pragma unroll
            for (int j = 0; j < 4; j++) b2[j] = pack2(bv[2 * j], bv[2 * j + 1]);
#pragma unroll
            for (int i = 0; i < 8; i++) {
                u64 a2 = pack2(a[i], a[i]);
#pragma unroll
                for (int j = 0; j < 4; j++) fma2(acc2[i][j], a2, b2[j]);
            }
        }
        __syncthreads();
    }

    float acc[8][8];
#pragma unroll
    for (int i = 0; i < 8; i++)
#pragma unroll
        for (int j = 0; j < 4; j++) {
            float2 f = unpack2(acc2[i][j]);
            acc[i][2 * j] = f.x; acc[i][2 * j + 1] = f.y;
        }

#pragma unroll
    for (int i = 0; i < 8; i++) {
        int r = row0 + ((i < 4) ? ((ty << 2) + i) : (64 + (ty << 2) + i - 4));
        float sqr = sq[b * NN + r];
#pragma unroll
        for (int j = 0; j < 8; j++) {
            int c = col0 + ((j < 4) ? ((tx << 2) + j) : (64 + (tx << 2) + j - 4));
            float v = sqr + sq[b * NN + c] - 2.f * acc[i][j];
            if (r == c) v = FLT_MAX;
            acc[i][j] = v;
        }
    }

    float* d2b = d2 + (size_t)b * NN * NN;
#pragma unroll
    for (int i = 0; i < 8; i++) {
        int r = row0 + ((i < 4) ? ((ty << 2) + i) : (64 + (ty << 2) + i - 4));
        float4 v0 = make_float4(acc[i][0], acc[i][1], acc[i][2], acc[i][3]);
        float4 v1 = make_float4(acc[i][4], acc[i][5], acc[i][6], acc[i][7]);
        *(float4*)&d2b[(size_t)r * NN + col0 + (tx << 2)]      = v0;
        *(float4*)&d2b[(size_t)r * NN + col0 + 64 + (tx << 2)] = v1;
    }
    if (bi != bj) {
#pragma unroll
        for (int j = 0; j < 8; j++) {
            int c = col0 + ((j < 4) ? ((tx << 2) + j) : (64 + (tx << 2) + j - 4));
            float4 lo = make_float4(acc[0][j], acc[1][j], acc[2][j], acc[3][j]);
            float4 hi = make_float4(acc[4][j], acc[5][j], acc[6][j], acc[7][j]);
            *(float4*)&d2b[(size_t)c * NN + row0 + (ty << 2)]      = lo;
            *(float4*)&d2b[(size_t)c * NN + row0 + 64 + (ty << 2)] = hi;
        }
    }
}

// ---------------- top-K via 3-pass radix select (register-resident keys) ------
__global__ void __launch_bounds__(256)
knn_kernel(const float* __restrict__ d2, int* __restrict__ idxout) {
    __shared__ int hist[2048];
    __shared__ int wsum[8], wsumex[8];
    __shared__ int ctrlB, ctrlBelow;
    __shared__ int cnt, eqcnt;

    int p = blockIdx.x;
    int t = threadIdx.x, lane = t & 31, wid = t >> 5;

    const float4* row4 = (const float4*)(d2 + (size_t)p * NN);
    unsigned key[8];
#pragma unroll
    for (int u = 0; u < 2; u++) {
        float4 f = row4[t + (u << 8)];
        unsigned bx;
        bx = __float_as_uint(f.x); key[u * 4 + 0] = (bx & 0x80000000u) ? ~bx : (bx | 0x80000000u);
        bx = __float_as_uint(f.y); key[u * 4 + 1] = (bx & 0x80000000u) ? ~bx : (bx | 0x80000000u);
        bx = __float_as_uint(f.z); key[u * 4 + 2] = (bx & 0x80000000u) ? ~bx : (bx | 0x80000000u);
        bx = __float_as_uint(f.w); key[u * 4 + 3] = (bx & 0x80000000u) ? ~bx : (bx | 0x80000000u);
    }

    unsigned pval = 0, pmask = 0;
    int base = 0;
#pragma unroll
    for (int pass = 0; pass < 3; pass++) {
        const int shift = (pass == 0) ? 21 : (pass == 1) ? 10 : 0;
        const int nbins = (pass == 2) ? 1024 : 2048;
        for (int i = t; i < nbins; i += 256) hist[i] = 0;
        __syncthreads();
#pragma unroll
        for (int e = 0; e < 8; e++) {
            unsigned k = key[e];
            if ((k & pmask) == pval) atomicAdd(&hist[(k >> shift) & (nbins - 1)], 1);
        }
        __syncthreads();
        const int seg = nbins >> 8;
        const int b0 = t * seg;
        int s = 0;
        for (int j = 0; j < seg; j++) s += hist[b0 + j];
        int incl = s;
#pragma unroll
        for (int off = 1; off < 32; off <<= 1) {
            int n = __shfl_up_sync(0xffffffffu, incl, off);
            if (lane >= off) incl += n;
        }
        if (lane == 31) wsum[wid] = incl;
        __syncthreads();
        if (t == 0) {
            int run = 0;
            for (int w = 0; w < 8; w++) { wsumex[w] = run; run += wsum[w]; }
        }
        __syncthreads();
        int excl = wsumex[wid] + incl - s;
        int need = KNBR - base;
        if (excl < need && need <= excl + s) {
            int run = excl;
            for (int j = 0; j < seg; j++) {
                int c = hist[b0 + j];
                if (run + c >= need) { ctrlB = b0 + j; ctrlBelow = run; break; }
                run += c;
            }
        }
        __syncthreads();
        base += ctrlBelow;
        pval |= ((unsigned)ctrlB) << shift;
        pmask |= ((unsigned)(nbins - 1)) << shift;
        __syncthreads();
    }

    const unsigned T = pval;
    if (t == 0) { cnt = 0; eqcnt = 0; }
    __syncthreads();
#pragma unroll
    for (int e = 0; e < 8; e++) {
        unsigned k = key[e];
        int i = (t << 2) + ((e >> 2) << 10) + (e & 3);
        if (k < T) {
            int pos = atomicAdd(&cnt, 1);
            idxout[p * KNBR + pos] = i;
        } else if (k == T) {
            int q = atomicAdd(&eqcnt, 1);
            hist[q] = i;
        }
    }
    __syncthreads();
    int c = cnt, E = eqcnt, tn = KNBR - c;
    if (E == tn) {
        for (int j = t; j < E; j += 256) idxout[p * KNBR + c + j] = hist[j];
    } else {
        for (int j = t; j < E; j += 256) {
            int mi = hist[j], r = 0;
            for (int q = 0; q < E; q++) r += (hist[q] < mi);
            if (r < tn) idxout[p * KNBR + c + r] = mi;
        }
    }
}

// ---------------- combined weight prep: wc = [Wb | Wa - Wb] -------------------
__global__ void prepw_kernel(const float* __restrict__ W, float* __restrict__ wc,
                             int C, int Cout) {
    int i = blockIdx.x * blockDim.x + threadIdx.x;
    if (i < C * Cout) {
        int c = i / Cout, d = i % Cout;
        float wa = W[c * Cout + d];
        float wb = W[(C + c) * Cout + d];
        wc[c * (2 * Cout) + d] = wb;
        wc[c * (2 * Cout) + Cout + d] = wa - wb;
    }
}

// ---------------- generic GEMM with FFMA2 inner loop ---------------------------
__global__ void __launch_bounds__(256, 2)
gemm_kernel(const float* __restrict__ A, const float* __restrict__ Bm,
            float* __restrict__ Cm, int Kd, int Nd) {
    __shared__ __align__(16) float As[16][132];
    __shared__ __align__(16) float Bs[16][132];
    int row0 = blockIdx.y * 128, col0 = blockIdx.x * 128;
    int tid = threadIdx.x;
    int ty = tid >> 4, tx = tid & 15;
    u64 acc2[8][4];
#pragma unroll
    for (int i = 0; i < 8; i++)
#pragma unroll
        for (int j = 0; j < 4; j++) acc2[i][j] = 0ull;

    int kk = tid & 15, i0 = tid >> 4;
    int j0 = tid & 127, kb = tid >> 7;

    for (int k0 = 0; k0 < Kd; k0 += 16) {
        int k = k0 + kk;
        bool kin = (k < Kd);
#pragma unroll
        for (int u = 0; u < 8; u++) {
            int i = i0 + (u << 4);
            As[kk][i] = kin ? A[(size_t)(row0 + i) * Kd + k] : 0.f;
        }
#pragma unroll
        for (int u = 0; u < 8; u++) {
            int kr = kb + (u << 1);
            int kg = k0 + kr;
            Bs[kr][j0] = (kg < Kd) ? Bm[(size_t)kg * Nd + col0 + j0] : 0.f;
        }
        __syncthreads();
#pragma unroll
        for (int t = 0; t < 16; t++) {
            float a[8], bv[8];
            *(float4*)&a[0]  = *(const float4*)&As[t][ty << 2];
            *(float4*)&a[4]  = *(const float4*)&As[t][64 + (ty << 2)];
            *(float4*)&bv[0] = *(const float4*)&Bs[t][tx << 2];
            *(float4*)&bv[4] = *(const float4*)&Bs[t][64 + (tx << 2)];
            u64 b2[4];
#pragma unroll
            for (int j = 0; j < 4; j++) b2[j] = pack2(bv[2 * j], bv[2 * j + 1]);
#pragma unroll
            for (int i = 0; i < 8; i++) {
                u64 a2 = pack2(a[i], a[i]);
#pragma unroll
                for (int j = 0; j < 4; j++) fma2(acc2[i][j], a2, b2[j]);
            }
        }
        __syncthreads();
    }
#pragma unroll
    for (int i = 0; i < 8; i++) {
        int r = row0 + ((i < 4) ? ((ty << 2) + i) : (64 + (ty << 2) + i - 4));
        float2 f0 = unpack2(acc2[i][0]), f1 = unpack2(acc2[i][1]);
        float2 f2 = unpack2(acc2[i][2]), f3 = unpack2(acc2[i][3]);
        float4 v0 = make_float4(f0.x, f0.y, f1.x, f1.y);
        float4 v1 = make_float4(f2.x, f2.y, f3.x, f3.y);
        *(float4*)&Cm[(size_t)r * Nd + col0 + (tx << 2)]      = v0;
        *(float4*)&Cm[(size_t)r * Nd + col0 + 64 + (tx << 2)] = v1;
    }
}

// ---------------- gather-max + bias + activation (float4) ---------------------
__global__ void gather_kernel(const float* __restrict__ qp, const int* __restrict__ idx,
                              const float* __restrict__ bias, float* __restrict__ out,
                              int Cout, int relu) {
    __shared__ int nbr[KNBR];
    int p = blockIdx.x;
    int b = p / NN;
    if (threadIdx.x < KNBR) nbr[threadIdx.x] = idx[p * KNBR + threadIdx.x];
    __syncthreads();
    int c4 = Cout >> 2;
    int ld4 = c4 << 1;
    const float4* qp4 = (const float4*)qp;
    const float4* b4  = (const float4*)bias;
    float4* out4 = (float4*)out;
    size_t baserow = (size_t)b * NN;
    for (int d = threadIdx.x; d < c4; d += blockDim.x) {
        float4 m = make_float4(-FLT_MAX, -FLT_MAX, -FLT_MAX, -FLT_MAX);
#pragma unroll 4
        for (int j = 0; j < KNBR; j++) {
            float4 v = qp4[(baserow + nbr[j]) * ld4 + d];
            m.x = fmaxf(m.x, v.x); m.y = fmaxf(m.y, v.y);
            m.z = fmaxf(m.z, v.z); m.w = fmaxf(m.w, v.w);
        }
        float4 pp = qp4[(size_t)p * ld4 + c4 + d];
        float4 bb = b4[d];
        float4 r;
        r.x = pp.x + bb.x + m.x; r.y = pp.y + bb.y + m.y;
        r.z = pp.z + bb.z + m.z; r.w = pp.w + bb.w + m.w;
        if (relu) {
            r.x = fmaxf(r.x, 0.f); r.y = fmaxf(r.y, 0.f);
            r.z = fmaxf(r.z, 0.f); r.w = fmaxf(r.w, 0.f);
        }
        out4[(size_t)p * c4 + d] = r;
    }
}

// ---------------- concat x1 | x2 (float4) --------------------------------------
__global__ void concat_kernel(const float* __restrict__ x1, const float* __restrict__ x2,
                              float* __restrict__ xc) {
    int i = blockIdx.x * blockDim.x + threadIdx.x;
    if (i < NPTS * 48) {
        int p = i / 48, c = i % 48;
        float4 v = (c < 16) ? ((const float4*)x1)[p * 16 + c]
                            : ((const float4*)x2)[p * 32 + (c - 16)];
        ((float4*)xc)[i] = v;
    }
}

// ---------------- launch ------------------------------------------------------
extern "C" void kernel_launch(void* const* d_in, const int* in_sizes, int n_in,
                              void* d_out, int out_size) {
    const float* x  = (const float*)d_in[0];
    const float* W1 = (const float*)d_in[1];
    const float* b1 = (const float*)d_in[2];
    const float* W2 = (const float*)d_in[3];
    const float* b2 = (const float*)d_in[4];
    const float* W3 = (const float*)d_in[5];
    const float* b3 = (const float*)d_in[6];
    float* out = (float*)d_out;

    float *d2, *sqp, *x1, *x2, *xc, *qp, *wc;
    int* idxp;
    cudaGetSymbolAddress((void**)&d2,   g_d2);
    cudaGetSymbolAddress((void**)&sqp,  g_sq);
    cudaGetSymbolAddress((void**)&idxp, g_idx);
    cudaGetSymbolAddress((void**)&x1,   g_x1);
    cudaGetSymbolAddress((void**)&x2,   g_x2);
    cudaGetSymbolAddress((void**)&xc,   g_xc);
    cudaGetSymbolAddress((void**)&qp,   g_qp);
    cudaGetSymbolAddress((void**)&wc,   g_wc);

    dim3 symgrid(NPAIR, BB);

    // ---- stage 1: C=3 -> 64  (knn placed 4th so ncu lands on it)
    sq_kernel<<<(NPTS + 255) / 256, 256>>>(x, sqp, 3);
    prepw_kernel<<<(3 * 64 + 255) / 256, 256>>>(W1, wc, 3, 64);
    d2sym_kernel<<<symgrid, 256>>>(x, sqp, d2, 3);
    knn_kernel<<<NPTS, 256>>>(d2, idxp);
    gemm_kernel<<<dim3(128 / 128, NPTS / 128), 256>>>(x, wc, qp, 3, 128);
    gather_kernel<<<NPTS, 32>>>(qp, idxp, b1, x1, 64, 1);

    // ---- stage 2: C=64 -> 128
    sq_kernel<<<(NPTS + 255) / 256, 256>>>(x1, sqp, 64);
    prepw_kernel<<<(64 * 128 + 255) / 256, 256>>>(W2, wc, 64, 128);
    gemm_kernel<<<dim3(256 / 128, NPTS / 128), 256>>>(x1, wc, qp, 64, 256);
    d2sym_kernel<<<symgrid, 256>>>(x1, sqp, d2, 64);
    knn_kernel<<<NPTS, 256>>>(d2, idxp);
    gather_kernel<<<NPTS, 32>>>(qp, idxp, b2, x2, 128, 1);

    // ---- stage 3: knn on x2 (C=128), conv on concat(x1,x2) (C=192) -> 512
    sq_kernel<<<(NPTS + 255) / 256, 256>>>(x2, sqp, 128);
    d2sym_kernel<<<symgrid, 256>>>(x2, sqp, d2, 128);
    knn_kernel<<<NPTS, 256>>>(d2, idxp);
    concat_kernel<<<(NPTS * 48 + 255) / 256, 256>>>(x1, x2, xc);
    prepw_kernel<<<(192 * 512 + 255) / 256, 256>>>(W3, wc, 192, 512);
    gemm_kernel<<<dim3(1024 / 128, NPTS / 128), 256>>>(xc, wc, qp, 192, 1024);
    gather_kernel<<<NPTS, 128>>>(qp, idxp, b3, out, 512, 0);
}

// round 6
// speedup vs baseline: 3.5863x; 1.1740x over previous
#include <cuda_runtime.h>
#include <cfloat>

#define BB 8
#define NN 2048
#define KNBR 32
#define NPTS (BB*NN)
#define NBLK (NN/128)           // 16 tiles per dim
#define NPAIR (NBLK*(NBLK+1)/2) // 136 upper-tri block pairs

typedef unsigned long long u64;

__device__ __forceinline__ u64 pack2(float lo, float hi) {
    u64 r;
    asm("mov.b64 %0, {%1, %2};" : "=l"(r) : "f"(lo), "f"(hi));
    return r;
}
__device__ __forceinline__ float2 unpack2(u64 v) {
    float2 f;
    asm("mov.b64 {%0, %1}, %2;" : "=f"(f.x), "=f"(f.y) : "l"(v));
    return f;
}
__device__ __forceinline__ void fma2(u64& d, u64 a, u64 b) {
    asm("fma.rn.f32x2 %0, %1, %2, %0;" : "+l"(d) : "l"(a), "l"(b));
}

// ---------------- scratch (static device globals; no runtime alloc) ----------
__device__ float g_d2[(size_t)NPTS * NN];    // 134MB pairwise distances (reused per stage)
__device__ float g_sq[NPTS];
__device__ int   g_idx[NPTS * KNBR];
__device__ float g_x1[NPTS * 64];
__device__ float g_x2[NPTS * 128];
__device__ float g_xc[NPTS * 192];
__device__ float g_qp[(size_t)NPTS * 1024];  // [q | p] per point, max 2*512
__device__ float g_wc[192 * 1024];           // combined weights [Wb | Wa-Wb]

// ---------------- squared norms ----------------------------------------------
__global__ void sq_kernel(const float* __restrict__ X, float* __restrict__ sq, int C) {
    int i = blockIdx.x * blockDim.x + threadIdx.x;
    if (i < NPTS) {
        const float* r = X + (size_t)i * C;
        float s = 0.f;
        for (int c = 0; c < C; c++) s += r[c] * r[c];
        sq[i] = s;
    }
}

// ---------------- pairwise d2, symmetric, FFMA2 inner loop --------------------
__global__ void __launch_bounds__(256, 2)
d2sym_kernel(const float* __restrict__ X, const float* __restrict__ sq,
             float* __restrict__ d2, int C) {
    __shared__ __align__(16) float As[16][132];
    __shared__ __align__(16) float Bs[16][132];
    int b = blockIdx.y;
    int rem = blockIdx.x, bi = 0;
    while (rem >= NBLK - bi) { rem -= NBLK - bi; bi++; }
    int bj = bi + rem;
    int row0 = bi * 128, col0 = bj * 128;

    const float* Xb = X + (size_t)b * NN * C;
    int tid = threadIdx.x;
    int ty = tid >> 4, tx = tid & 15;
    u64 acc2[8][4];
#pragma unroll
    for (int i = 0; i < 8; i++)
#pragma unroll
        for (int j = 0; j < 4; j++) acc2[i][j] = 0ull;

    int kk = tid & 15, i0 = tid >> 4;

    for (int k0 = 0; k0 < C; k0 += 16) {
        int k = k0 + kk;
        bool kin = (k < C);
#pragma unroll
        for (int u = 0; u < 8; u++) {
            int i = i0 + (u << 4);
            As[kk][i] = kin ? Xb[(size_t)(row0 + i) * C + k] : 0.f;
            Bs[kk][i] = kin ? Xb[(size_t)(col0 + i) * C + k] : 0.f;
        }
        __syncthreads();
#pragma unroll
        for (int t = 0; t < 16; t++) {
            float a[8], bv[8];
            *(float4*)&a[0]  = *(const float4*)&As[t][ty << 2];
            *(float4*)&a[4]  = *(const float4*)&As[t][64 + (ty << 2)];
            *(float4*)&bv[0] = *(const float4*)&Bs[t][tx << 2];
            *(float4*)&bv[4] = *(const float4*)&Bs[t][64 + (tx << 2)];
            u64 b2[4];
#pragma unroll
            for (int j = 0; j < 4; j++) b2[j] = pack2(bv[2 * j], bv[2 * j + 1]);
#pragma unroll
            for (int i = 0; i < 8; i++) {
                u64 a2 = pack2(a[i], a[i]);
#pragma unroll
                for (int j = 0; j < 4; j++) fma2(acc2[i][j], a2, b2[j]);
            }
        }
        __syncthreads();
    }

    float acc[8][8];
#pragma unroll
    for (int i = 0; i < 8; i++)
#pragma unroll
        for (int j = 0; j < 4; j++) {
            float2 f = unpack2(acc2[i][j]);
            acc[i][2 * j] = f.x; acc[i][2 * j + 1] = f.y;
        }

#pragma unroll
    for (int i = 0; i < 8; i++) {
        int r = row0 + ((i < 4) ? ((ty << 2) + i) : (64 + (ty << 2) + i - 4));
        float sqr = sq[b * NN + r];
#pragma unroll
        for (int j = 0; j < 8; j++) {
            int c = col0 + ((j < 4) ? ((tx << 2) + j) : (64 + (tx << 2) + j - 4));
            float v = sqr + sq[b * NN + c] - 2.f * acc[i][j];
            if (r == c) v = FLT_MAX;
            acc[i][j] = v;
        }
    }

    float* d2b = d2 + (size_t)b * NN * NN;
#pragma unroll
    for (int i = 0; i < 8; i++) {
        int r = row0 + ((i < 4) ? ((ty << 2) + i) : (64 + (ty << 2) + i - 4));
        float4 v0 = make_float4(acc[i][0], acc[i][1], acc[i][2], acc[i][3]);
        float4 v1 = make_float4(acc[i][4], acc[i][5], acc[i][6], acc[i][7]);
        *(float4*)&d2b[(size_t)r * NN + col0 + (tx << 2)]      = v0;
        *(float4*)&d2b[(size_t)r * NN + col0 + 64 + (tx << 2)] = v1;
    }
    if (bi != bj) {
#pragma unroll
        for (int j = 0; j < 8; j++) {
            int c = col0 + ((j < 4) ? ((tx << 2) + j) : (64 + (tx << 2) + j - 4));
            float4 lo = make_float4(acc[0][j], acc[1][j], acc[2][j], acc[3][j]);
            float4 hi = make_float4(acc[4][j], acc[5][j], acc[6][j], acc[7][j]);
            *(float4*)&d2b[(size_t)c * NN + row0 + (ty << 2)]      = lo;
            *(float4*)&d2b[(size_t)c * NN + row0 + 64 + (ty << 2)] = hi;
        }
    }
}

// ---------------- top-K via 4-pass (8-bit) radix select ------------------------
// 256 bins/pass: zero = 1 STS/thread, scan = plain warp scan of 1 value/thread.
// Pass 1 uses __match_any_sync warp aggregation to kill hot-bin atomic serialization.
__global__ void __launch_bounds__(256)
knn_kernel(const float* __restrict__ d2, int* __restrict__ idxout) {
    __shared__ int hist[2048];      // 256 used as bins; full 2048 reused as tie buffer
    __shared__ int wsum[8], wsumex[8];
    __shared__ int ctrlB, ctrlBelow;
    __shared__ int cnt, eqcnt;

    int p = blockIdx.x;
    int t = threadIdx.x, lane = t & 31, wid = t >> 5;

    const float4* row4 = (const float4*)(d2 + (size_t)p * NN);
    unsigned key[8];
#pragma unroll
    for (int u = 0; u < 2; u++) {
        float4 f = row4[t + (u << 8)];
        unsigned bx;
        bx = __float_as_uint(f.x); key[u * 4 + 0] = (bx & 0x80000000u) ? ~bx : (bx | 0x80000000u);
        bx = __float_as_uint(f.y); key[u * 4 + 1] = (bx & 0x80000000u) ? ~bx : (bx | 0x80000000u);
        bx = __float_as_uint(f.z); key[u * 4 + 2] = (bx & 0x80000000u) ? ~bx : (bx | 0x80000000u);
        bx = __float_as_uint(f.w); key[u * 4 + 3] = (bx & 0x80000000u) ? ~bx : (bx | 0x80000000u);
    }

    unsigned pval = 0, pmask = 0;
    int base = 0;
#pragma unroll
    for (int pass = 0; pass < 4; pass++) {
        const int shift = 24 - (pass << 3);
        hist[t] = 0;
        __syncthreads();
        if (pass == 0) {
            // all keys active: warp-aggregated histogram
#pragma unroll
            for (int e = 0; e < 8; e++) {
                int bin = key[e] >> 24;
                unsigned peers = __match_any_sync(0xffffffffu, bin);
                int leader = __ffs(peers) - 1;
                if (lane == leader) atomicAdd(&hist[bin], __popc(peers));
            }
        } else {
#pragma unroll
            for (int e = 0; e < 8; e++) {
                unsigned k = key[e];
                if ((k & pmask) == pval) atomicAdd(&hist[(k >> shift) & 255], 1);
            }
        }
        __syncthreads();
        int s = hist[t];
        int incl = s;
#pragma unroll
        for (int off = 1; off < 32; off <<= 1) {
            int n = __shfl_up_sync(0xffffffffu, incl, off);
            if (lane >= off) incl += n;
        }
        if (lane == 31) wsum[wid] = incl;
        __syncthreads();
        if (t == 0) {
            int run = 0;
            for (int w = 0; w < 8; w++) { wsumex[w] = run; run += wsum[w]; }
        }
        __syncthreads();
        int excl = wsumex[wid] + incl - s;
        int need = KNBR - base;
        if (excl < need && need <= excl + s) {   // exactly one thread matches
            ctrlB = t; ctrlBelow = excl;
        }
        __syncthreads();
        base += ctrlBelow;
        pval |= ((unsigned)ctrlB) << shift;
        pmask |= 255u << shift;
        __syncthreads();   // ctrl/hist rewritten next pass
    }

    const unsigned T = pval;               // exact key value of the 32nd smallest
    if (t == 0) { cnt = 0; eqcnt = 0; }
    __syncthreads();
#pragma unroll
    for (int e = 0; e < 8; e++) {
        unsigned k = key[e];
        int i = (t << 2) + ((e >> 2) << 10) + (e & 3);
        if (k < T) {
            int pos = atomicAdd(&cnt, 1);
            idxout[p * KNBR + pos] = i;
        } else if (k == T) {
            int q = atomicAdd(&eqcnt, 1);
            hist[q] = i;                    // tie buffer (<= 2048 entries)
        }
    }
    __syncthreads();
    int c = cnt, E = eqcnt, tn = KNBR - c;  // tn >= 1 by construction
    if (E == tn) {
        for (int j = t; j < E; j += 256) idxout[p * KNBR + c + j] = hist[j];
    } else {
        for (int j = t; j < E; j += 256) {
            int mi = hist[j], r = 0;
            for (int q = 0; q < E; q++) r += (hist[q] < mi);
            if (r < tn) idxout[p * KNBR + c + r] = mi;
        }
    }
}

// ---------------- combined weight prep: wc = [Wb | Wa - Wb] -------------------
__global__ void prepw_kernel(const float* __restrict__ W, float* __restrict__ wc,
                             int C, int Cout) {
    int i = blockIdx.x * blockDim.x + threadIdx.x;
    if (i < C * Cout) {
        int c = i / Cout, d = i % Cout;
        float wa = W[c * Cout + d];
        float wb = W[(C + c) * Cout + d];
        wc[c * (2 * Cout) + d] = wb;
        wc[c * (2 * Cout) + Cout + d] = wa - wb;
    }
}

// ---------------- generic GEMM with FFMA2 inner loop ---------------------------
__global__ void __launch_bounds__(256, 2)
gemm_kernel(const float* __restrict__ A, const float* __restrict__ Bm,
            float* __restrict__ Cm, int Kd, int Nd) {
    __shared__ __align__(16) float As[16][132];
    __shared__ __align__(16) float Bs[16][132];
    int row0 = blockIdx.y * 128, col0 = blockIdx.x * 128;
    int tid = threadIdx.x;
    int ty = tid >> 4, tx = tid & 15;
    u64 acc2[8][4];
#pragma unroll
    for (int i = 0; i < 8; i++)
#pragma unroll
        for (int j = 0; j < 4; j++) acc2[i][j] = 0ull;

    int kk = tid & 15, i0 = tid >> 4;
    int j0 = tid & 127, kb = tid >> 7;

    for (int k0 = 0; k0 < Kd; k0 += 16) {
        int k = k0 + kk;
        bool kin = (k < Kd);
#pragma unroll
        for (int u = 0; u < 8; u++) {
            int i = i0 + (u << 4);
            As[kk][i] = kin ? A[(size_t)(row0 + i) * Kd + k] : 0.f;
        }
#pragma unroll
        for (int u = 0; u < 8; u++) {
            int kr = kb + (u << 1);
            int kg = k0 + kr;
            Bs[kr][j0] = (kg < Kd) ? Bm[(size_t)kg * Nd + col0 + j0] : 0.f;
        }
        __syncthreads();
#pragma unroll
        for (int t = 0; t < 16; t++) {
            float a[8], bv[8];
            *(float4*)&a[0]  = *(const float4*)&As[t][ty << 2];
            *(float4*)&a[4]  = *(const float4*)&As[t][64 + (ty << 2)];
            *(float4*)&bv[0] = *(const float4*)&Bs[t][tx << 2];
            *(float4*)&bv[4] = *(const float4*)&Bs[t][64 + (tx << 2)];
            u64 b2[4];
#pragma unroll
            for (int j = 0; j < 4; j++) b2[j] = pack2(bv[2 * j], bv[2 * j + 1]);
#pragma unroll
            for (int i = 0; i < 8; i++) {
                u64 a2 = pack2(a[i], a[i]);
#pragma unroll
                for (int j = 0; j < 4; j++) fma2(acc2[i][j], a2, b2[j]);
            }
        }
        __syncthreads();
    }
#pragma unroll
    for (int i = 0; i < 8; i++) {
        int r = row0 + ((i < 4) ? ((ty << 2) + i) : (64 + (ty << 2) + i - 4));
        float2 f0 = unpack2(acc2[i][0]), f1 = unpack2(acc2[i][1]);
        float2 f2 = unpack2(acc2[i][2]), f3 = unpack2(acc2[i][3]);
        float4 v0 = make_float4(f0.x, f0.y, f1.x, f1.y);
        float4 v1 = make_float4(f2.x, f2.y, f3.x, f3.y);
        *(float4*)&Cm[(size_t)r * Nd + col0 + (tx << 2)]      = v0;
        *(float4*)&Cm[(size_t)r * Nd + col0 + 64 + (tx << 2)] = v1;
    }
}

// ---------------- gather-max + bias + activation (float4) ---------------------
__global__ void gather_kernel(const float* __restrict__ qp, const int* __restrict__ idx,
                              const float* __restrict__ bias, float* __restrict__ out,
                              int Cout, int relu) {
    __shared__ int nbr[KNBR];
    int p = blockIdx.x;
    int b = p / NN;
    if (threadIdx.x < KNBR) nbr[threadIdx.x] = idx[p * KNBR + threadIdx.x];
    __syncthreads();
    int c4 = Cout >> 2;
    int ld4 = c4 << 1;
    const float4* qp4 = (const float4*)qp;
    const float4* b4  = (const float4*)bias;
    float4* out4 = (float4*)out;
    size_t baserow = (size_t)b * NN;
    for (int d = threadIdx.x; d < c4; d += blockDim.x) {
        float4 m = make_float4(-FLT_MAX, -FLT_MAX, -FLT_MAX, -FLT_MAX);
#pragma unroll 4
        for (int j = 0; j < KNBR; j++) {
            float4 v = qp4[(baserow + nbr[j]) * ld4 + d];
            m.x = fmaxf(m.x, v.x); m.y = fmaxf(m.y, v.y);
            m.z = fmaxf(m.z, v.z); m.w = fmaxf(m.w, v.w);
        }
        float4 pp = qp4[(size_t)p * ld4 + c4 + d];
        float4 bb = b4[d];
        float4 r;
        r.x = pp.x + bb.x + m.x; r.y = pp.y + bb.y + m.y;
        r.z = pp.z + bb.z + m.z; r.w = pp.w + bb.w + m.w;
        if (relu) {
            r.x = fmaxf(r.x, 0.f); r.y = fmaxf(r.y, 0.f);
            r.z = fmaxf(r.z, 0.f); r.w = fmaxf(r.w, 0.f);
        }
        out4[(size_t)p * c4 + d] = r;
    }
}

// ---------------- concat x1 | x2 (float4) --------------------------------------
__global__ void concat_kernel(const float* __restrict__ x1, const float* __restrict__ x2,
                              float* __restrict__ xc) {
    int i = blockIdx.x * blockDim.x + threadIdx.x;
    if (i < NPTS * 48) {
        int p = i / 48, c = i % 48;
        float4 v = (c < 16) ? ((const float4*)x1)[p * 16 + c]
                            : ((const float4*)x2)[p * 32 + (c - 16)];
        ((float4*)xc)[i] = v;
    }
}

// ---------------- launch ------------------------------------------------------
extern "C" void kernel_launch(void* const* d_in, const int* in_sizes, int n_in,
                              void* d_out, int out_size) {
    const float* x  = (const float*)d_in[0];
    const float* W1 = (const float*)d_in[1];
    const float* b1 = (const float*)d_in[2];
    const float* W2 = (const float*)d_in[3];
    const float* b2 = (const float*)d_in[4];
    const float* W3 = (const float*)d_in[5];
    const float* b3 = (const float*)d_in[6];
    float* out = (float*)d_out;

    float *d2, *sqp, *x1, *x2, *xc, *qp, *wc;
    int* idxp;
    cudaGetSymbolAddress((void**)&d2,   g_d2);
    cudaGetSymbolAddress((void**)&sqp,  g_sq);
    cudaGetSymbolAddress((void**)&idxp, g_idx);
    cudaGetSymbolAddress((void**)&x1,   g_x1);
    cudaGetSymbolAddress((void**)&x2,   g_x2);
    cudaGetSymbolAddress((void**)&xc,   g_xc);
    cudaGetSymbolAddress((void**)&qp,   g_qp);
    cudaGetSymbolAddress((void**)&wc,   g_wc);

    dim3 symgrid(NPAIR, BB);

    // ---- stage 1: C=3 -> 64  (knn placed 4th so ncu lands on it)
    sq_kernel<<<(NPTS + 255) / 256, 256>>>(x, sqp, 3);
    prepw_kernel<<<(3 * 64 + 255) / 256, 256>>>(W1, wc, 3, 64);
    d2sym_kernel<<<symgrid, 256>>>(x, sqp, d2, 3);
    knn_kernel<<<NPTS, 256>>>(d2, idxp);
    gemm_kernel<<<dim3(128 / 128, NPTS / 128), 256>>>(x, wc, qp, 3, 128);
    gather_kernel<<<NPTS, 32>>>(qp, idxp, b1, x1, 64, 1);

    // ---- stage 2: C=64 -> 128
    sq_kernel<<<(NPTS + 255) / 256, 256>>>(x1, sqp, 64);
    prepw_kernel<<<(64 * 128 + 255) / 256, 256>>>(W2, wc, 64, 128);
    gemm_kernel<<<dim3(256 / 128, NPTS / 128), 256>>>(x1, wc, qp, 64, 256);
    d2sym_kernel<<<symgrid, 256>>>(x1, sqp, d2, 64);
    knn_kernel<<<NPTS, 256>>>(d2, idxp);
    gather_kernel<<<NPTS, 32>>>(qp, idxp, b2, x2, 128, 1);

    // ---- stage 3: knn on x2 (C=128), conv on concat(x1,x2) (C=192) -> 512
    sq_kernel<<<(NPTS + 255) / 256, 256>>>(x2, sqp, 128);
    d2sym_kernel<<<symgrid, 256>>>(x2, sqp, d2, 128);
    knn_kernel<<<NPTS, 256>>>(d2, idxp);
    concat_kernel<<<(NPTS * 48 + 255) / 256, 256>>>(x1, x2, xc);
    prepw_kernel<<<(192 * 512 + 255) / 256, 256>>>(W3, wc, 192, 512);
    gemm_kernel<<<dim3(1024 / 128, NPTS / 128), 256>>>(xc, wc, qp, 192, 1024);
    gather_kernel<<<NPTS, 128>>>(qp, idxp, b3, out, 512, 0);
}